// round 1
// baseline (speedup 1.0000x reference)
#include <cuda_runtime.h>
#include <math.h>

#define S_LEN  1024
#define BATCH  8
#define DMODEL 256
#define NH     8
#define HDIM   32
#define DFF    1024
#define MROWS  (S_LEN * BATCH)   // 8192
#define LN_EPS 1e-5f

// ---------------- scratch (no runtime allocation allowed) ----------------
__device__ float g_x  [MROWS * DMODEL];       // LN1(src)
__device__ float g_qkv[MROWS * 3 * DMODEL];   // qkv projection
__device__ float g_q  [BATCH * NH * S_LEN * HDIM];
__device__ float g_k  [BATCH * NH * S_LEN * HDIM];
__device__ float g_v  [BATCH * NH * S_LEN * HDIM];
__device__ float g_ctx[MROWS * DMODEL];       // attention context, [S,B,D]
__device__ float g_x2 [MROWS * DMODEL];       // x + attn_out
__device__ float g_y  [MROWS * DMODEL];       // LN2(x2)
__device__ float g_ff1[MROWS * DFF];          // relu(y@w1^T+b1)

// ---------------- LayerNorm: one warp per row (D=256 -> 8 floats/lane) ----
__global__ void ln_kernel(const float* __restrict__ in,
                          const float* __restrict__ gw,
                          const float* __restrict__ bw,
                          float* __restrict__ out) {
    int row  = blockIdx.x * blockDim.y + threadIdx.y;
    int lane = threadIdx.x;
    const float4* xp = (const float4*)(in + (size_t)row * DMODEL);
    float4 v0 = xp[lane];
    float4 v1 = xp[lane + 32];
    float s = v0.x + v0.y + v0.z + v0.w + v1.x + v1.y + v1.z + v1.w;
#pragma unroll
    for (int o = 16; o > 0; o >>= 1) s += __shfl_xor_sync(0xffffffffu, s, o);
    float mu = s * (1.0f / DMODEL);
    float d0x = v0.x - mu, d0y = v0.y - mu, d0z = v0.z - mu, d0w = v0.w - mu;
    float d1x = v1.x - mu, d1y = v1.y - mu, d1z = v1.z - mu, d1w = v1.w - mu;
    float q = d0x*d0x + d0y*d0y + d0z*d0z + d0w*d0w
            + d1x*d1x + d1y*d1y + d1z*d1z + d1w*d1w;
#pragma unroll
    for (int o = 16; o > 0; o >>= 1) q += __shfl_xor_sync(0xffffffffu, q, o);
    float rs = rsqrtf(q * (1.0f / DMODEL) + LN_EPS);
    const float4* gp = (const float4*)gw;
    const float4* bp = (const float4*)bw;
    float4 ga = gp[lane], gb = gp[lane + 32];
    float4 ba = bp[lane], bb = bp[lane + 32];
    float4 o0, o1;
    o0.x = d0x * rs * ga.x + ba.x;  o0.y = d0y * rs * ga.y + ba.y;
    o0.z = d0z * rs * ga.z + ba.z;  o0.w = d0w * rs * ga.w + ba.w;
    o1.x = d1x * rs * gb.x + bb.x;  o1.y = d1y * rs * gb.y + bb.y;
    o1.z = d1z * rs * gb.z + bb.z;  o1.w = d1w * rs * gb.w + bb.w;
    float4* op = (float4*)(out + (size_t)row * DMODEL);
    op[lane]      = o0;
    op[lane + 32] = o1;
}

// ---------------- SGEMM: C[M,N] = A[M,K] @ W[N,K]^T + bias (+relu)(+resid) --
// BM=BN=128, BK=16, 256 threads, each thread computes a 2x4 x 2x4 = 8x8 tile
// split as rows {ty*4+i, 64+ty*4+i}, cols {tx*4+j, 64+tx*4+j} (conflict-free
// float4 LDS on both operands).
template<bool RELU, bool RESID>
__global__ void sgemm_kernel(const float* __restrict__ A,
                             const float* __restrict__ W,
                             const float* __restrict__ bias,
                             const float* __restrict__ resid,
                             float* __restrict__ C, int K, int N) {
    constexpr int BM = 128, BN = 128, BK = 16;
    __shared__ float As[BM][BK];
    __shared__ float Bs[BK][BN];
    int tid = threadIdx.x;
    int tx = tid & 15, ty = tid >> 4;
    int rowBase = blockIdx.y * BM;
    int colBase = blockIdx.x * BN;
    int lr = tid >> 2;          // 0..63
    int lk = (tid & 3) << 2;    // 0,4,8,12
    const float* Ap = A + (size_t)(rowBase + lr) * K + lk;
    const float* Wp = W + (size_t)(colBase + lr) * K + lk;

    float acc[2][4][2][4];
#pragma unroll
    for (int rh = 0; rh < 2; rh++)
#pragma unroll
        for (int i = 0; i < 4; i++)
#pragma unroll
            for (int ch = 0; ch < 2; ch++)
#pragma unroll
                for (int j = 0; j < 4; j++) acc[rh][i][ch][j] = 0.0f;

    for (int k0 = 0; k0 < K; k0 += BK) {
        float4 a0 = *(const float4*)(Ap + k0);
        float4 a1 = *(const float4*)(Ap + k0 + (size_t)64 * K);
        float4 w0 = *(const float4*)(Wp + k0);
        float4 w1 = *(const float4*)(Wp + k0 + (size_t)64 * K);
        *(float4*)&As[lr][lk]      = a0;
        *(float4*)&As[lr + 64][lk] = a1;
        Bs[lk + 0][lr] = w0.x; Bs[lk + 1][lr] = w0.y;
        Bs[lk + 2][lr] = w0.z; Bs[lk + 3][lr] = w0.w;
        Bs[lk + 0][lr + 64] = w1.x; Bs[lk + 1][lr + 64] = w1.y;
        Bs[lk + 2][lr + 64] = w1.z; Bs[lk + 3][lr + 64] = w1.w;
        __syncthreads();
#pragma unroll
        for (int kk = 0; kk < BK; kk += 4) {
            float4 a[8];
#pragma unroll
            for (int rh = 0; rh < 2; rh++)
#pragma unroll
                for (int i = 0; i < 4; i++)
                    a[rh * 4 + i] = *(const float4*)&As[rh * 64 + ty * 4 + i][kk];
#pragma unroll
            for (int u = 0; u < 4; u++) {
                float4 b0 = *(const float4*)&Bs[kk + u][tx * 4];
                float4 b1 = *(const float4*)&Bs[kk + u][64 + tx * 4];
#pragma unroll
                for (int rh = 0; rh < 2; rh++)
#pragma unroll
                    for (int i = 0; i < 4; i++) {
                        float av = ((const float*)&a[rh * 4 + i])[u];
                        acc[rh][i][0][0] += av * b0.x;
                        acc[rh][i][0][1] += av * b0.y;
                        acc[rh][i][0][2] += av * b0.z;
                        acc[rh][i][0][3] += av * b0.w;
                        acc[rh][i][1][0] += av * b1.x;
                        acc[rh][i][1][1] += av * b1.y;
                        acc[rh][i][1][2] += av * b1.z;
                        acc[rh][i][1][3] += av * b1.w;
                    }
            }
        }
        __syncthreads();
    }

#pragma unroll
    for (int rh = 0; rh < 2; rh++)
#pragma unroll
        for (int i = 0; i < 4; i++) {
            int r = rowBase + rh * 64 + ty * 4 + i;
#pragma unroll
            for (int ch = 0; ch < 2; ch++) {
                int c = colBase + ch * 64 + tx * 4;
                float4 o;
                o.x = acc[rh][i][ch][0] + bias[c + 0];
                o.y = acc[rh][i][ch][1] + bias[c + 1];
                o.z = acc[rh][i][ch][2] + bias[c + 2];
                o.w = acc[rh][i][ch][3] + bias[c + 3];
                if (RELU) {
                    o.x = fmaxf(o.x, 0.0f); o.y = fmaxf(o.y, 0.0f);
                    o.z = fmaxf(o.z, 0.0f); o.w = fmaxf(o.w, 0.0f);
                }
                if (RESID) {
                    float4 rr = *(const float4*)&resid[(size_t)r * N + c];
                    o.x += rr.x; o.y += rr.y; o.z += rr.z; o.w += rr.w;
                }
                *(float4*)&C[(size_t)r * N + c] = o;
            }
        }
}

// ---------------- repack qkv [S*B, 3*D] -> q/k/v [B,H,S,HD], scale q -------
__global__ void repack_kernel(const float* __restrict__ qkv,
                              float* __restrict__ q,
                              float* __restrict__ k,
                              float* __restrict__ v) {
    int idx  = blockIdx.x * 256 + threadIdx.x;   // float4 index
    int col4 = idx % 192;
    int row  = idx / 192;
    int s = row >> 3;          // / BATCH
    int b = row & 7;
    int col  = col4 * 4;
    int part = col >> 8;
    int hh   = (col & 255) >> 5;
    int hd   = col & 31;
    float4 val = ((const float4*)qkv)[idx];
    size_t dsti = (((((size_t)b * NH + hh) * S_LEN + s) * HDIM) + hd) >> 2;
    if (part == 0) {
        const float sc = 0.17677669529663687f;   // 1/sqrt(32)
        val.x *= sc; val.y *= sc; val.z *= sc; val.w *= sc;
        ((float4*)q)[dsti] = val;
    } else if (part == 1) {
        ((float4*)k)[dsti] = val;
    } else {
        ((float4*)v)[dsti] = val;
    }
}

// ---------------- flash attention with additive bias ----------------------
// grid (S/64, B*H); block 256 (tx 0..15, ty 0..15).
// Thread owns score rows ty*4..+4, score cols tx*4..+4, ctx cols tx*2..+2.
__global__ void attn_kernel(const float* __restrict__ Q,
                            const float* __restrict__ Kg,
                            const float* __restrict__ Vg,
                            const float* __restrict__ bias,
                            float* __restrict__ ctx) {
    __shared__ float Qs[64][HDIM];
    __shared__ float Ks[64][HDIM];
    __shared__ float Vs[64][HDIM];
    __shared__ float Ps[64][64];
    int bh = blockIdx.y;
    int b  = bh >> 3, h = bh & 7;
    int qt  = blockIdx.x;
    int tid = threadIdx.x;
    int tx = tid & 15, ty = tid >> 4;
    const float* qb = Q  + (size_t)bh * S_LEN * HDIM + (size_t)qt * 64 * HDIM;
    const float* kb = Kg + (size_t)bh * S_LEN * HDIM;
    const float* vb = Vg + (size_t)bh * S_LEN * HDIM;
    const float* biasb = bias + ((size_t)bh * S_LEN + (size_t)qt * 64) * S_LEN;

    ((float4*)Qs)[tid]       = ((const float4*)qb)[tid];
    ((float4*)Qs)[tid + 256] = ((const float4*)qb)[tid + 256];

    float m[4], l[4], acc0[4], acc1[4];
#pragma unroll
    for (int i = 0; i < 4; i++) { m[i] = -1e30f; l[i] = 0.0f; acc0[i] = 0.0f; acc1[i] = 0.0f; }

    for (int j = 0; j < S_LEN / 64; j++) {
        __syncthreads();   // previous iteration's PV done; Qs ready (j==0)
        const float4* ksrc = (const float4*)(kb + (size_t)j * 64 * HDIM);
        const float4* vsrc = (const float4*)(vb + (size_t)j * 64 * HDIM);
        ((float4*)Ks)[tid]       = ksrc[tid];
        ((float4*)Ks)[tid + 256] = ksrc[tid + 256];
        ((float4*)Vs)[tid]       = vsrc[tid];
        ((float4*)Vs)[tid + 256] = vsrc[tid + 256];
        __syncthreads();

        // scores = bias + Q K^T
        float s[4][4];
#pragma unroll
        for (int i = 0; i < 4; i++) {
            float4 bb = *(const float4*)(biasb + (size_t)(ty * 4 + i) * S_LEN + j * 64 + tx * 4);
            s[i][0] = bb.x; s[i][1] = bb.y; s[i][2] = bb.z; s[i][3] = bb.w;
        }
#pragma unroll
        for (int kk = 0; kk < HDIM; kk += 4) {
            float4 qv[4], kv[4];
#pragma unroll
            for (int i = 0; i < 4; i++)  qv[i] = *(const float4*)&Qs[ty * 4 + i][kk];
#pragma unroll
            for (int jj = 0; jj < 4; jj++) kv[jj] = *(const float4*)&Ks[tx * 4 + jj][kk];
#pragma unroll
            for (int i = 0; i < 4; i++)
#pragma unroll
                for (int jj = 0; jj < 4; jj++)
                    s[i][jj] += qv[i].x * kv[jj].x + qv[i].y * kv[jj].y
                              + qv[i].z * kv[jj].z + qv[i].w * kv[jj].w;
        }

        // online softmax (row groups live in 16-lane shuffle groups)
#pragma unroll
        for (int i = 0; i < 4; i++) {
            float mi = fmaxf(fmaxf(s[i][0], s[i][1]), fmaxf(s[i][2], s[i][3]));
#pragma unroll
            for (int o = 1; o < 16; o <<= 1)
                mi = fmaxf(mi, __shfl_xor_sync(0xffffffffu, mi, o));
            float mn   = fmaxf(m[i], mi);
            float corr = __expf(m[i] - mn);
            float ps = 0.0f;
#pragma unroll
            for (int jj = 0; jj < 4; jj++) {
                float p = __expf(s[i][jj] - mn);
                s[i][jj] = p; ps += p;
            }
#pragma unroll
            for (int o = 1; o < 16; o <<= 1)
                ps += __shfl_xor_sync(0xffffffffu, ps, o);
            l[i] = l[i] * corr + ps;
            m[i] = mn;
            acc0[i] *= corr; acc1[i] *= corr;
            *(float4*)&Ps[ty * 4 + i][tx * 4] = make_float4(s[i][0], s[i][1], s[i][2], s[i][3]);
        }
        __syncthreads();

        // ctx += P @ V   (each thread: 4 rows x 2 hd-cols)
#pragma unroll
        for (int t4 = 0; t4 < 64; t4 += 4) {
            float2 vv0 = *(const float2*)&Vs[t4 + 0][tx * 2];
            float2 vv1 = *(const float2*)&Vs[t4 + 1][tx * 2];
            float2 vv2 = *(const float2*)&Vs[t4 + 2][tx * 2];
            float2 vv3 = *(const float2*)&Vs[t4 + 3][tx * 2];
#pragma unroll
            for (int i = 0; i < 4; i++) {
                float4 p = *(const float4*)&Ps[ty * 4 + i][t4];
                acc0[i] += p.x * vv0.x + p.y * vv1.x + p.z * vv2.x + p.w * vv3.x;
                acc1[i] += p.x * vv0.y + p.y * vv1.y + p.z * vv2.y + p.w * vv3.y;
            }
        }
    }

    // write ctx in [S,B,D] with d = h*HD + hd
#pragma unroll
    for (int i = 0; i < 4; i++) {
        int srow = qt * 64 + ty * 4 + i;
        float inv = 1.0f / l[i];
        float2 o = make_float2(acc0[i] * inv, acc1[i] * inv);
        *(float2*)&ctx[((size_t)srow * BATCH + b) * DMODEL + h * HDIM + tx * 2] = o;
    }
}

// ---------------- launch ---------------------------------------------------
extern "C" void kernel_launch(void* const* d_in, const int* in_sizes, int n_in,
                              void* d_out, int out_size) {
    const float* src   = (const float*)d_in[0];
    const float* bias  = (const float*)d_in[1];
    const float* in_w  = (const float*)d_in[2];
    const float* in_b  = (const float*)d_in[3];
    const float* out_w = (const float*)d_in[4];
    const float* out_b = (const float*)d_in[5];
    const float* w1    = (const float*)d_in[6];
    const float* b1    = (const float*)d_in[7];
    const float* w2    = (const float*)d_in[8];
    const float* b2    = (const float*)d_in[9];
    const float* g1    = (const float*)d_in[10];
    const float* be1   = (const float*)d_in[11];
    const float* g2    = (const float*)d_in[12];
    const float* be2   = (const float*)d_in[13];
    float* out = (float*)d_out;

    float *px, *pqkv, *pq, *pk, *pv, *pctx, *px2, *py, *pff1;
    cudaGetSymbolAddress((void**)&px,   g_x);
    cudaGetSymbolAddress((void**)&pqkv, g_qkv);
    cudaGetSymbolAddress((void**)&pq,   g_q);
    cudaGetSymbolAddress((void**)&pk,   g_k);
    cudaGetSymbolAddress((void**)&pv,   g_v);
    cudaGetSymbolAddress((void**)&pctx, g_ctx);
    cudaGetSymbolAddress((void**)&px2,  g_x2);
    cudaGetSymbolAddress((void**)&py,   g_y);
    cudaGetSymbolAddress((void**)&pff1, g_ff1);

    dim3 lnb(32, 8);
    // 1. x = LN1(src)
    ln_kernel<<<MROWS / 8, lnb>>>(src, g1, be1, px);
    // 2. qkv = x @ in_proj_w^T + in_proj_b
    sgemm_kernel<false, false><<<dim3(6, 64), 256>>>(px, in_w, in_b, nullptr, pqkv, DMODEL, 3 * DMODEL);
    // 3. repack to heads (+ q scaling)
    repack_kernel<<<6144, 256>>>(pqkv, pq, pk, pv);
    // 4. flash attention with bias -> ctx [S,B,D]
    attn_kernel<<<dim3(16, 64), 256>>>(pq, pk, pv, bias, pctx);
    // 5. x2 = x + ctx @ out_w^T + out_b
    sgemm_kernel<false, true><<<dim3(2, 64), 256>>>(pctx, out_w, out_b, px, px2, DMODEL, DMODEL);
    // 6. y = LN2(x2)
    ln_kernel<<<MROWS / 8, lnb>>>(px2, g2, be2, py);
    // 7. ff1 = relu(y @ w1^T + b1)
    sgemm_kernel<true, false><<<dim3(8, 64), 256>>>(py, w1, b1, nullptr, pff1, DMODEL, DFF);
    // 8. out = y + ff1 @ w2^T + b2
    sgemm_kernel<false, true><<<dim3(2, 64), 256>>>(pff1, w2, b2, py, out, DFF, DMODEL);
}

// round 4
// speedup vs baseline: 1.8842x; 1.8842x over previous
#include <cuda_runtime.h>
#include <cstdint>
#include <math.h>

#define S_LEN  1024
#define BATCH  8
#define DMODEL 256
#define NH     8
#define HDIM   32
#define DFF    1024
#define MROWS  (S_LEN * BATCH)   // 8192
#define LN_EPS 1e-5f

// ---------------- scratch (no runtime allocation allowed) ----------------
__device__ float g_x  [MROWS * DMODEL];
__device__ float g_qkv[MROWS * 3 * DMODEL];
__device__ float g_q  [BATCH * NH * S_LEN * HDIM];
__device__ float g_k  [BATCH * NH * S_LEN * HDIM];
__device__ float g_v  [BATCH * NH * S_LEN * HDIM];
__device__ float g_ctx[MROWS * DMODEL];
__device__ float g_x2 [MROWS * DMODEL];
__device__ float g_y  [MROWS * DMODEL];
__device__ float g_ff1[MROWS * DFF];

// ---------------- mma.sync tf32 helpers (sm_80+, works on sm_100 target) --
__device__ __forceinline__ void mma1688(float* c, const uint32_t* a, uint32_t b0, uint32_t b1) {
    asm volatile(
        "mma.sync.aligned.m16n8k8.row.col.f32.tf32.tf32.f32 "
        "{%0,%1,%2,%3}, {%4,%5,%6,%7}, {%8,%9}, {%0,%1,%2,%3};"
        : "+f"(c[0]), "+f"(c[1]), "+f"(c[2]), "+f"(c[3])
        : "r"(a[0]), "r"(a[1]), "r"(a[2]), "r"(a[3]), "r"(b0), "r"(b1));
}
__device__ __forceinline__ uint32_t hibits(float x) {
    return __float_as_uint(x) & 0xFFFFE000u;
}
__device__ __forceinline__ float hival(float x) {
    return __uint_as_float(__float_as_uint(x) & 0xFFFFE000u);
}

// ---------------- LayerNorm: one warp per row ----------------------------
__global__ void ln_kernel(const float* __restrict__ in,
                          const float* __restrict__ gw,
                          const float* __restrict__ bw,
                          float* __restrict__ out) {
    int row  = blockIdx.x * blockDim.y + threadIdx.y;
    int lane = threadIdx.x;
    const float4* xp = (const float4*)(in + (size_t)row * DMODEL);
    float4 v0 = xp[lane];
    float4 v1 = xp[lane + 32];
    float s = v0.x + v0.y + v0.z + v0.w + v1.x + v1.y + v1.z + v1.w;
#pragma unroll
    for (int o = 16; o > 0; o >>= 1) s += __shfl_xor_sync(0xffffffffu, s, o);
    float mu = s * (1.0f / DMODEL);
    float d0x = v0.x - mu, d0y = v0.y - mu, d0z = v0.z - mu, d0w = v0.w - mu;
    float d1x = v1.x - mu, d1y = v1.y - mu, d1z = v1.z - mu, d1w = v1.w - mu;
    float q = d0x*d0x + d0y*d0y + d0z*d0z + d0w*d0w
            + d1x*d1x + d1y*d1y + d1z*d1z + d1w*d1w;
#pragma unroll
    for (int o = 16; o > 0; o >>= 1) q += __shfl_xor_sync(0xffffffffu, q, o);
    float rs = rsqrtf(q * (1.0f / DMODEL) + LN_EPS);
    const float4* gp = (const float4*)gw;
    const float4* bp = (const float4*)bw;
    float4 ga = gp[lane], gb = gp[lane + 32];
    float4 ba = bp[lane], bb = bp[lane + 32];
    float4 o0, o1;
    o0.x = d0x * rs * ga.x + ba.x;  o0.y = d0y * rs * ga.y + ba.y;
    o0.z = d0z * rs * ga.z + ba.z;  o0.w = d0w * rs * ga.w + ba.w;
    o1.x = d1x * rs * gb.x + bb.x;  o1.y = d1y * rs * gb.y + bb.y;
    o1.z = d1z * rs * gb.z + bb.z;  o1.w = d1w * rs * gb.w + bb.w;
    float4* op = (float4*)(out + (size_t)row * DMODEL);
    op[lane]      = o0;
    op[lane + 32] = o1;
}

// ---------------- SGEMM (round-1 proven) ----------------------------------
template<bool RELU, bool RESID>
__global__ void sgemm_kernel(const float* __restrict__ A,
                             const float* __restrict__ W,
                             const float* __restrict__ bias,
                             const float* __restrict__ resid,
                             float* __restrict__ C, int K, int N) {
    constexpr int BM = 128, BN = 128, BK = 16;
    __shared__ float As[BM][BK];
    __shared__ float Bs[BK][BN];
    int tid = threadIdx.x;
    int tx = tid & 15, ty = tid >> 4;
    int rowBase = blockIdx.y * BM;
    int colBase = blockIdx.x * BN;
    int lr = tid >> 2;
    int lk = (tid & 3) << 2;
    const float* Ap = A + (size_t)(rowBase + lr) * K + lk;
    const float* Wp = W + (size_t)(colBase + lr) * K + lk;

    float acc[2][4][2][4];
#pragma unroll
    for (int rh = 0; rh < 2; rh++)
#pragma unroll
        for (int i = 0; i < 4; i++)
#pragma unroll
            for (int ch = 0; ch < 2; ch++)
#pragma unroll
                for (int j = 0; j < 4; j++) acc[rh][i][ch][j] = 0.0f;

    for (int k0 = 0; k0 < K; k0 += BK) {
        float4 a0 = *(const float4*)(Ap + k0);
        float4 a1 = *(const float4*)(Ap + k0 + (size_t)64 * K);
        float4 w0 = *(const float4*)(Wp + k0);
        float4 w1 = *(const float4*)(Wp + k0 + (size_t)64 * K);
        *(float4*)&As[lr][lk]      = a0;
        *(float4*)&As[lr + 64][lk] = a1;
        Bs[lk + 0][lr] = w0.x; Bs[lk + 1][lr] = w0.y;
        Bs[lk + 2][lr] = w0.z; Bs[lk + 3][lr] = w0.w;
        Bs[lk + 0][lr + 64] = w1.x; Bs[lk + 1][lr + 64] = w1.y;
        Bs[lk + 2][lr + 64] = w1.z; Bs[lk + 3][lr + 64] = w1.w;
        __syncthreads();
#pragma unroll
        for (int kk = 0; kk < BK; kk += 4) {
            float4 a[8];
#pragma unroll
            for (int rh = 0; rh < 2; rh++)
#pragma unroll
                for (int i = 0; i < 4; i++)
                    a[rh * 4 + i] = *(const float4*)&As[rh * 64 + ty * 4 + i][kk];
#pragma unroll
            for (int u = 0; u < 4; u++) {
                float4 b0 = *(const float4*)&Bs[kk + u][tx * 4];
                float4 b1 = *(const float4*)&Bs[kk + u][64 + tx * 4];
#pragma unroll
                for (int rh = 0; rh < 2; rh++)
#pragma unroll
                    for (int i = 0; i < 4; i++) {
                        float av = ((const float*)&a[rh * 4 + i])[u];
                        acc[rh][i][0][0] += av * b0.x;
                        acc[rh][i][0][1] += av * b0.y;
                        acc[rh][i][0][2] += av * b0.z;
                        acc[rh][i][0][3] += av * b0.w;
                        acc[rh][i][1][0] += av * b1.x;
                        acc[rh][i][1][1] += av * b1.y;
                        acc[rh][i][1][2] += av * b1.z;
                        acc[rh][i][1][3] += av * b1.w;
                    }
            }
        }
        __syncthreads();
    }

#pragma unroll
    for (int rh = 0; rh < 2; rh++)
#pragma unroll
        for (int i = 0; i < 4; i++) {
            int r = rowBase + rh * 64 + ty * 4 + i;
#pragma unroll
            for (int ch = 0; ch < 2; ch++) {
                int c = colBase + ch * 64 + tx * 4;
                float4 o;
                o.x = acc[rh][i][ch][0] + bias[c + 0];
                o.y = acc[rh][i][ch][1] + bias[c + 1];
                o.z = acc[rh][i][ch][2] + bias[c + 2];
                o.w = acc[rh][i][ch][3] + bias[c + 3];
                if (RELU) {
                    o.x = fmaxf(o.x, 0.0f); o.y = fmaxf(o.y, 0.0f);
                    o.z = fmaxf(o.z, 0.0f); o.w = fmaxf(o.w, 0.0f);
                }
                if (RESID) {
                    float4 rr = *(const float4*)&resid[(size_t)r * N + c];
                    o.x += rr.x; o.y += rr.y; o.z += rr.z; o.w += rr.w;
                }
                *(float4*)&C[(size_t)r * N + c] = o;
            }
        }
}

// ---------------- repack qkv [S*B, 3*D] -> q/k/v [B,H,S,HD], scale q -------
__global__ void repack_kernel(const float* __restrict__ qkv,
                              float* __restrict__ q,
                              float* __restrict__ k,
                              float* __restrict__ v) {
    int idx  = blockIdx.x * 256 + threadIdx.x;
    int col4 = idx % 192;
    int row  = idx / 192;
    int s = row >> 3;
    int b = row & 7;
    int col  = col4 * 4;
    int part = col >> 8;
    int hh   = (col & 255) >> 5;
    int hd   = col & 31;
    float4 val = ((const float4*)qkv)[idx];
    size_t dsti = (((((size_t)b * NH + hh) * S_LEN + s) * HDIM) + hd) >> 2;
    if (part == 0) {
        const float sc = 0.17677669529663687f;
        val.x *= sc; val.y *= sc; val.z *= sc; val.w *= sc;
        ((float4*)q)[dsti] = val;
    } else if (part == 1) {
        ((float4*)k)[dsti] = val;
    } else {
        ((float4*)v)[dsti] = val;
    }
}

// ================= mma.sync tf32 flash attention ==========================
// Block 256 threads = 8 warps; warp owns 16 q-rows. BM=128, chunk BN=64.
// Split-tf32 (hi/lo) 3-MMA emulation for both QK^T and PV.
// smem: Ks[64][36] fp32, Vt[32][68] fp32 (transposed), Ps[128][68] fp32.
#define AKS 0
#define AVT (64 * 36)
#define APS (AVT + 32 * 68)
#define ATOT_FLOATS (APS + 128 * 68)
#define ATOT_BYTES (ATOT_FLOATS * 4)     // 52736

__global__ void __launch_bounds__(256) attn_mma_kernel(
    const float* __restrict__ Qg, const float* __restrict__ Kg,
    const float* __restrict__ Vg, const float* __restrict__ biasg,
    float* __restrict__ ctx)
{
    extern __shared__ float sm[];
    float* Ks = sm + AKS;
    float* Vt = sm + AVT;
    float* Ps = sm + APS;

    int tid  = threadIdx.x;
    int warp = tid >> 5, lane = tid & 31;
    int g = lane >> 2, q4 = lane & 3;
    int bh = blockIdx.y, qt = blockIdx.x;
    int b = bh >> 3, h = bh & 7;
    int rowbase = warp * 16;
    int rA = rowbase + g;        // local row (0..127)
    int rB = rA + 8;

    const float* qb = Qg + ((size_t)bh * S_LEN + (size_t)qt * 128) * HDIM;
    const float* kb = Kg + (size_t)bh * S_LEN * HDIM;
    const float* vb = Vg + (size_t)bh * S_LEN * HDIM;
    const float* biasA = biasg + ((size_t)bh * S_LEN + (size_t)(qt * 128 + rA)) * S_LEN;
    const float* biasB = biasA + (size_t)8 * S_LEN;

    // ---- Q fragments (held in regs for whole kernel), split hi/lo ----
    uint32_t qh[4][4], ql[4][4];
#pragma unroll
    for (int kt = 0; kt < 4; kt++) {
        float a0 = qb[rA * HDIM + kt * 8 + q4];
        float a1 = qb[rB * HDIM + kt * 8 + q4];
        float a2 = qb[rA * HDIM + kt * 8 + q4 + 4];
        float a3 = qb[rB * HDIM + kt * 8 + q4 + 4];
        qh[kt][0] = hibits(a0); ql[kt][0] = __float_as_uint(a0 - hival(a0));
        qh[kt][1] = hibits(a1); ql[kt][1] = __float_as_uint(a1 - hival(a1));
        qh[kt][2] = hibits(a2); ql[kt][2] = __float_as_uint(a2 - hival(a2));
        qh[kt][3] = hibits(a3); ql[kt][3] = __float_as_uint(a3 - hival(a3));
    }

    float mA = -1e30f, mB = -1e30f, lA = 0.0f, lB = 0.0f;
    float o[4][4];
#pragma unroll
    for (int nt = 0; nt < 4; nt++)
#pragma unroll
        for (int i = 0; i < 4; i++) o[nt][i] = 0.0f;

    int tld = tid >> 2;             // 0..63 (token row for loads)
    int dld = (tid & 3) * 8;        // 0,8,16,24 (dim part)

    for (int j = 0; j < 16; j++) {
        // ---- stage K chunk (row-major padded) + V chunk (transposed) ----
        {
            const float* krow = kb + (size_t)(j * 64 + tld) * HDIM + dld;
            float4 k0 = *(const float4*)(krow);
            float4 k1 = *(const float4*)(krow + 4);
            *(float4*)(Ks + tld * 36 + dld)     = k0;
            *(float4*)(Ks + tld * 36 + dld + 4) = k1;
            const float* vrow = vb + (size_t)(j * 64 + tld) * HDIM + dld;
            float4 v0 = *(const float4*)(vrow);
            float4 v1 = *(const float4*)(vrow + 4);
            Vt[(dld + 0) * 68 + tld] = v0.x; Vt[(dld + 1) * 68 + tld] = v0.y;
            Vt[(dld + 2) * 68 + tld] = v0.z; Vt[(dld + 3) * 68 + tld] = v0.w;
            Vt[(dld + 4) * 68 + tld] = v1.x; Vt[(dld + 5) * 68 + tld] = v1.y;
            Vt[(dld + 6) * 68 + tld] = v1.z; Vt[(dld + 7) * 68 + tld] = v1.w;
        }
        __syncthreads();

        // ---- C fragments initialized with bias (read once from DRAM) ----
        float c[8][4];
#pragma unroll
        for (int nt = 0; nt < 8; nt++) {
            float2 bA = *(const float2*)(biasA + j * 64 + nt * 8 + 2 * q4);
            float2 bB = *(const float2*)(biasB + j * 64 + nt * 8 + 2 * q4);
            c[nt][0] = bA.x; c[nt][1] = bA.y; c[nt][2] = bB.x; c[nt][3] = bB.y;
        }

        // ---- QK^T (split-tf32: Ahi*Bhi + Ahi*Blo + Alo*Bhi) ----
#pragma unroll
        for (int nt = 0; nt < 8; nt++) {
#pragma unroll
            for (int kt = 0; kt < 4; kt++) {
                float b0 = Ks[(nt * 8 + g) * 36 + kt * 8 + q4];
                float b1 = Ks[(nt * 8 + g) * 36 + kt * 8 + q4 + 4];
                uint32_t bh0 = hibits(b0), bh1 = hibits(b1);
                uint32_t bl0 = __float_as_uint(b0 - hival(b0));
                uint32_t bl1 = __float_as_uint(b1 - hival(b1));
                mma1688(c[nt], qh[kt], bh0, bh1);
                mma1688(c[nt], qh[kt], bl0, bl1);
                mma1688(c[nt], ql[kt], bh0, bh1);
            }
        }

        // ---- online softmax (thread owns rows rA, rB; quad = 4 lanes) ----
        float mxA = -1e30f, mxB = -1e30f;
#pragma unroll
        for (int nt = 0; nt < 8; nt++) {
            mxA = fmaxf(mxA, fmaxf(c[nt][0], c[nt][1]));
            mxB = fmaxf(mxB, fmaxf(c[nt][2], c[nt][3]));
        }
        mxA = fmaxf(mxA, __shfl_xor_sync(0xffffffffu, mxA, 1));
        mxA = fmaxf(mxA, __shfl_xor_sync(0xffffffffu, mxA, 2));
        mxB = fmaxf(mxB, __shfl_xor_sync(0xffffffffu, mxB, 1));
        mxB = fmaxf(mxB, __shfl_xor_sync(0xffffffffu, mxB, 2));
        float nmA = fmaxf(mA, mxA), nmB = fmaxf(mB, mxB);
        float corrA = __expf(mA - nmA), corrB = __expf(mB - nmB);
        mA = nmA; mB = nmB;
        float sA = 0.0f, sB = 0.0f;
#pragma unroll
        for (int nt = 0; nt < 8; nt++) {
            float p0 = __expf(c[nt][0] - nmA);
            float p1 = __expf(c[nt][1] - nmA);
            float p2 = __expf(c[nt][2] - nmB);
            float p3 = __expf(c[nt][3] - nmB);
            sA += p0 + p1; sB += p2 + p3;
            *(float2*)(Ps + rA * 68 + nt * 8 + 2 * q4) = make_float2(p0, p1);
            *(float2*)(Ps + rB * 68 + nt * 8 + 2 * q4) = make_float2(p2, p3);
        }
        sA += __shfl_xor_sync(0xffffffffu, sA, 1);
        sA += __shfl_xor_sync(0xffffffffu, sA, 2);
        sB += __shfl_xor_sync(0xffffffffu, sB, 1);
        sB += __shfl_xor_sync(0xffffffffu, sB, 2);
        lA = lA * corrA + sA;
        lB = lB * corrB + sB;
#pragma unroll
        for (int nt = 0; nt < 4; nt++) {
            o[nt][0] *= corrA; o[nt][1] *= corrA;
            o[nt][2] *= corrB; o[nt][3] *= corrB;
        }
        __syncwarp();   // Ps rows are warp-private; warp-level visibility only

        // ---- PV (split-tf32) ----
#pragma unroll
        for (int kk = 0; kk < 8; kk++) {
            float a0 = Ps[rA * 68 + kk * 8 + q4];
            float a1 = Ps[rB * 68 + kk * 8 + q4];
            float a2 = Ps[rA * 68 + kk * 8 + q4 + 4];
            float a3 = Ps[rB * 68 + kk * 8 + q4 + 4];
            uint32_t ah[4] = { hibits(a0), hibits(a1), hibits(a2), hibits(a3) };
            uint32_t al[4] = { __float_as_uint(a0 - hival(a0)), __float_as_uint(a1 - hival(a1)),
                               __float_as_uint(a2 - hival(a2)), __float_as_uint(a3 - hival(a3)) };
#pragma unroll
            for (int nt = 0; nt < 4; nt++) {
                float b0 = Vt[(nt * 8 + g) * 68 + kk * 8 + q4];
                float b1 = Vt[(nt * 8 + g) * 68 + kk * 8 + q4 + 4];
                uint32_t bh0 = hibits(b0), bh1 = hibits(b1);
                uint32_t bl0 = __float_as_uint(b0 - hival(b0));
                uint32_t bl1 = __float_as_uint(b1 - hival(b1));
                mma1688(o[nt], ah, bh0, bh1);
                mma1688(o[nt], ah, bl0, bl1);
                mma1688(o[nt], al, bh0, bh1);
            }
        }
        __syncthreads();   // protect Ks/Vt for next chunk
    }

    // ---- epilogue: normalize and write ctx[S,B,D] ----
    float invA = 1.0f / lA, invB = 1.0f / lB;
    float* cA = ctx + ((size_t)(qt * 128 + rA) * BATCH + b) * DMODEL + h * HDIM;
    float* cB = ctx + ((size_t)(qt * 128 + rB) * BATCH + b) * DMODEL + h * HDIM;
#pragma unroll
    for (int nt = 0; nt < 4; nt++) {
        *(float2*)(cA + nt * 8 + 2 * q4) = make_float2(o[nt][0] * invA, o[nt][1] * invA);
        *(float2*)(cB + nt * 8 + 2 * q4) = make_float2(o[nt][2] * invB, o[nt][3] * invB);
    }
}

// ---------------- launch ---------------------------------------------------
extern "C" void kernel_launch(void* const* d_in, const int* in_sizes, int n_in,
                              void* d_out, int out_size) {
    const float* src   = (const float*)d_in[0];
    const float* bias  = (const float*)d_in[1];
    const float* in_w  = (const float*)d_in[2];
    const float* in_b  = (const float*)d_in[3];
    const float* out_w = (const float*)d_in[4];
    const float* out_b = (const float*)d_in[5];
    const float* w1    = (const float*)d_in[6];
    const float* b1    = (const float*)d_in[7];
    const float* w2    = (const float*)d_in[8];
    const float* b2    = (const float*)d_in[9];
    const float* g1    = (const float*)d_in[10];
    const float* be1   = (const float*)d_in[11];
    const float* g2    = (const float*)d_in[12];
    const float* be2   = (const float*)d_in[13];
    float* out = (float*)d_out;

    float *px, *pqkv, *pq, *pk, *pv, *pctx, *px2, *py, *pff1;
    cudaGetSymbolAddress((void**)&px,   g_x);
    cudaGetSymbolAddress((void**)&pqkv, g_qkv);
    cudaGetSymbolAddress((void**)&pq,   g_q);
    cudaGetSymbolAddress((void**)&pk,   g_k);
    cudaGetSymbolAddress((void**)&pv,   g_v);
    cudaGetSymbolAddress((void**)&pctx, g_ctx);
    cudaGetSymbolAddress((void**)&px2,  g_x2);
    cudaGetSymbolAddress((void**)&py,   g_y);
    cudaGetSymbolAddress((void**)&pff1, g_ff1);

    // Unconditional (no static guards per harness rules); >48KB dynamic smem.
    cudaFuncSetAttribute(attn_mma_kernel, cudaFuncAttributeMaxDynamicSharedMemorySize, ATOT_BYTES);

    dim3 lnb(32, 8);
    ln_kernel<<<MROWS / 8, lnb>>>(src, g1, be1, px);
    sgemm_kernel<false, false><<<dim3(6, 64), 256>>>(px, in_w, in_b, nullptr, pqkv, DMODEL, 3 * DMODEL);
    repack_kernel<<<6144, 256>>>(pqkv, pq, pk, pv);
    attn_mma_kernel<<<dim3(8, 64), 256, ATOT_BYTES>>>(pq, pk, pv, bias, pctx);
    sgemm_kernel<false, true><<<dim3(2, 64), 256>>>(pctx, out_w, out_b, px, px2, DMODEL, DMODEL);
    ln_kernel<<<MROWS / 8, lnb>>>(px2, g2, be2, py);
    sgemm_kernel<true, false><<<dim3(8, 64), 256>>>(py, w1, b1, nullptr, pff1, DMODEL, DFF);
    sgemm_kernel<false, true><<<dim3(2, 64), 256>>>(pff1, w2, b2, py, out, DFF, DMODEL);
}

// round 5
// speedup vs baseline: 2.6851x; 1.4250x over previous
#include <cuda_runtime.h>
#include <cuda_bf16.h>
#include <cstdint>
#include <math.h>

#define S_LEN  1024
#define BATCH  8
#define DMODEL 256
#define NH     8
#define HDIM   32
#define DFF    1024
#define MROWS  (S_LEN * BATCH)   // 8192
#define LN_EPS 1e-5f

// ---------------- scratch (no runtime allocation allowed) ----------------
__device__ float g_x  [MROWS * DMODEL];
__device__ float g_q  [BATCH * NH * S_LEN * HDIM];
__device__ float g_k  [BATCH * NH * S_LEN * HDIM];
__device__ float g_v  [BATCH * NH * S_LEN * HDIM];
__device__ float g_ctx[MROWS * DMODEL];
__device__ float g_x2 [MROWS * DMODEL];
__device__ float g_y  [MROWS * DMODEL];
__device__ float g_ff1[MROWS * DFF];

// ---------------- mma helpers ---------------------------------------------
__device__ __forceinline__ void mma1688(float* c, const uint32_t* a, uint32_t b0, uint32_t b1) {
    asm volatile(
        "mma.sync.aligned.m16n8k8.row.col.f32.tf32.tf32.f32 "
        "{%0,%1,%2,%3}, {%4,%5,%6,%7}, {%8,%9}, {%0,%1,%2,%3};"
        : "+f"(c[0]), "+f"(c[1]), "+f"(c[2]), "+f"(c[3])
        : "r"(a[0]), "r"(a[1]), "r"(a[2]), "r"(a[3]), "r"(b0), "r"(b1));
}
__device__ __forceinline__ void mma16816(float* c, const uint32_t* a, uint32_t b0, uint32_t b1) {
    asm volatile(
        "mma.sync.aligned.m16n8k16.row.col.f32.bf16.bf16.f32 "
        "{%0,%1,%2,%3}, {%4,%5,%6,%7}, {%8,%9}, {%0,%1,%2,%3};"
        : "+f"(c[0]), "+f"(c[1]), "+f"(c[2]), "+f"(c[3])
        : "r"(a[0]), "r"(a[1]), "r"(a[2]), "r"(a[3]), "r"(b0), "r"(b1));
}
__device__ __forceinline__ uint32_t hibits(float x) {
    return __float_as_uint(x) & 0xFFFFE000u;
}
__device__ __forceinline__ float hival(float x) {
    return __uint_as_float(__float_as_uint(x) & 0xFFFFE000u);
}
// split x,y into packed bf16x2 hi and lo (hi + lo ~= x with 16 mantissa bits)
__device__ __forceinline__ void split_bf16x2(float x, float y, uint32_t& hi, uint32_t& lo) {
    __nv_bfloat162 h = __floats2bfloat162_rn(x, y);
    float hx = __bfloat162float(h.x), hy = __bfloat162float(h.y);
    __nv_bfloat162 l = __floats2bfloat162_rn(x - hx, y - hy);
    hi = *reinterpret_cast<uint32_t*>(&h);
    lo = *reinterpret_cast<uint32_t*>(&l);
}

// ---------------- LayerNorm: one warp per row ----------------------------
__global__ void ln_kernel(const float* __restrict__ in,
                          const float* __restrict__ gw,
                          const float* __restrict__ bw,
                          float* __restrict__ out) {
    int row  = blockIdx.x * blockDim.y + threadIdx.y;
    int lane = threadIdx.x;
    const float4* xp = (const float4*)(in + (size_t)row * DMODEL);
    float4 v0 = xp[lane];
    float4 v1 = xp[lane + 32];
    float s = v0.x + v0.y + v0.z + v0.w + v1.x + v1.y + v1.z + v1.w;
#pragma unroll
    for (int o = 16; o > 0; o >>= 1) s += __shfl_xor_sync(0xffffffffu, s, o);
    float mu = s * (1.0f / DMODEL);
    float d0x = v0.x - mu, d0y = v0.y - mu, d0z = v0.z - mu, d0w = v0.w - mu;
    float d1x = v1.x - mu, d1y = v1.y - mu, d1z = v1.z - mu, d1w = v1.w - mu;
    float q = d0x*d0x + d0y*d0y + d0z*d0z + d0w*d0w
            + d1x*d1x + d1y*d1y + d1z*d1z + d1w*d1w;
#pragma unroll
    for (int o = 16; o > 0; o >>= 1) q += __shfl_xor_sync(0xffffffffu, q, o);
    float rs = rsqrtf(q * (1.0f / DMODEL) + LN_EPS);
    const float4* gp = (const float4*)gw;
    const float4* bp = (const float4*)bw;
    float4 ga = gp[lane], gb = gp[lane + 32];
    float4 ba = bp[lane], bb = bp[lane + 32];
    float4 o0, o1;
    o0.x = d0x * rs * ga.x + ba.x;  o0.y = d0y * rs * ga.y + ba.y;
    o0.z = d0z * rs * ga.z + ba.z;  o0.w = d0w * rs * ga.w + ba.w;
    o1.x = d1x * rs * gb.x + bb.x;  o1.y = d1y * rs * gb.y + bb.y;
    o1.z = d1z * rs * gb.z + bb.z;  o1.w = d1w * rs * gb.w + bb.w;
    float4* op = (float4*)(out + (size_t)row * DMODEL);
    op[lane]      = o0;
    op[lane + 32] = o1;
}

// ================= bf16-split tensor GEMM ==================================
// C[M,N] = A[M,K] @ W[N,K]^T (+bias)(+relu | +resid | scatter qkv)
// Block 128x128, BK=32, 256 threads = 8 warps (4 x 2), warp tile 32x64.
// smem tiles packed as bf16x2 k-pairs; row pad 20 uint32 (conflict-free frags).
// MODE: 0 = bias, 1 = bias+relu, 2 = bias+resid, 3 = qkv scatter (+q scale)
#define GP 20   // row pitch in uint32 (16 used)
template<int MODE>
__global__ void __launch_bounds__(256) gemm_bf16_kernel(
    const float* __restrict__ A, const float* __restrict__ W,
    const float* __restrict__ bias, const float* __restrict__ resid,
    float* __restrict__ C,
    float* __restrict__ qo, float* __restrict__ ko, float* __restrict__ vo,
    int K, int N)
{
    __shared__ uint32_t sAh[128 * GP], sAl[128 * GP];
    __shared__ uint32_t sWh[128 * GP], sWl[128 * GP];

    int tid = threadIdx.x;
    int warp = tid >> 5, lane = tid & 31;
    int g = lane >> 2, q4 = lane & 3;
    int wm = warp >> 1, wn = warp & 1;           // 4 x 2 warps
    int m0 = wm * 32, n0 = wn * 64;
    int rowBase = blockIdx.y * 128;
    int colBase = blockIdx.x * 128;

    int lr = tid >> 1;                 // 0..127
    int lc = (tid & 1) * 16;           // float offset within 32-float row piece
    const float* Ap = A + (size_t)(rowBase + lr) * K + lc;
    const float* Wp = W + (size_t)(colBase + lr) * K + lc;
    uint32_t* sAhp = sAh + lr * GP + (tid & 1) * 8;
    uint32_t* sAlp = sAl + lr * GP + (tid & 1) * 8;
    uint32_t* sWhp = sWh + lr * GP + (tid & 1) * 8;
    uint32_t* sWlp = sWl + lr * GP + (tid & 1) * 8;

    float c[2][8][4];
#pragma unroll
    for (int mt = 0; mt < 2; mt++)
#pragma unroll
        for (int nt = 0; nt < 8; nt++)
#pragma unroll
            for (int i = 0; i < 4; i++) c[mt][nt][i] = 0.0f;

    for (int k0 = 0; k0 < K; k0 += 32) {
        // ---- stage + split-convert A and W tiles ----
#pragma unroll
        for (int p = 0; p < 4; p++) {
            float4 av = *(const float4*)(Ap + k0 + p * 4);
            uint32_t h0, l0, h1, l1;
            split_bf16x2(av.x, av.y, h0, l0);
            split_bf16x2(av.z, av.w, h1, l1);
            sAhp[p * 2] = h0; sAhp[p * 2 + 1] = h1;
            sAlp[p * 2] = l0; sAlp[p * 2 + 1] = l1;
            float4 wv = *(const float4*)(Wp + k0 + p * 4);
            split_bf16x2(wv.x, wv.y, h0, l0);
            split_bf16x2(wv.z, wv.w, h1, l1);
            sWhp[p * 2] = h0; sWhp[p * 2 + 1] = h1;
            sWlp[p * 2] = l0; sWlp[p * 2 + 1] = l1;
        }
        __syncthreads();

#pragma unroll
        for (int ks = 0; ks < 2; ks++) {         // two k16 halves of BK=32
            int kb = ks * 8;
            uint32_t ah[2][4], al[2][4];
#pragma unroll
            for (int mt = 0; mt < 2; mt++) {
                int r0 = (m0 + mt * 16 + g) * GP + kb + q4;
                int r1 = (m0 + mt * 16 + g + 8) * GP + kb + q4;
                ah[mt][0] = sAh[r0];     ah[mt][1] = sAh[r1];
                ah[mt][2] = sAh[r0 + 4]; ah[mt][3] = sAh[r1 + 4];
                al[mt][0] = sAl[r0];     al[mt][1] = sAl[r1];
                al[mt][2] = sAl[r0 + 4]; al[mt][3] = sAl[r1 + 4];
            }
#pragma unroll
            for (int nt = 0; nt < 8; nt++) {
                int rb = (n0 + nt * 8 + g) * GP + kb + q4;
                uint32_t bh0 = sWh[rb], bh1 = sWh[rb + 4];
                uint32_t bl0 = sWl[rb], bl1 = sWl[rb + 4];
#pragma unroll
                for (int mt = 0; mt < 2; mt++) {
                    mma16816(c[mt][nt], ah[mt], bh0, bh1);
                    mma16816(c[mt][nt], ah[mt], bl0, bl1);
                    mma16816(c[mt][nt], al[mt], bh0, bh1);
                }
            }
        }
        __syncthreads();
    }

    // ---- epilogue ----
#pragma unroll
    for (int mt = 0; mt < 2; mt++) {
#pragma unroll
        for (int half = 0; half < 2; half++) {   // rows g / g+8
            int r = rowBase + m0 + mt * 16 + g + half * 8;
#pragma unroll
            for (int nt = 0; nt < 8; nt++) {
                int cc = colBase + n0 + nt * 8 + 2 * q4;
                float v0 = c[mt][nt][half * 2 + 0] + bias[cc];
                float v1 = c[mt][nt][half * 2 + 1] + bias[cc + 1];
                if (MODE == 1) { v0 = fmaxf(v0, 0.0f); v1 = fmaxf(v1, 0.0f); }
                if (MODE == 2) {
                    float2 rr = *(const float2*)&resid[(size_t)r * N + cc];
                    v0 += rr.x; v1 += rr.y;
                }
                if (MODE == 3) {
                    // r = s*BATCH+b ; cc = part*256 + h*32 + hd
                    int s = r >> 3, b = r & 7;
                    int part = cc >> 8;
                    int h = (cc & 255) >> 5;
                    int hd = cc & 31;
                    size_t dst = ((((size_t)b * NH + h) * S_LEN + s) * HDIM) + hd;
                    if (part == 0) {
                        const float sc = 0.17677669529663687f;  // 1/sqrt(32)
                        *(float2*)&qo[dst] = make_float2(v0 * sc, v1 * sc);
                    } else if (part == 1) {
                        *(float2*)&ko[dst] = make_float2(v0, v1);
                    } else {
                        *(float2*)&vo[dst] = make_float2(v0, v1);
                    }
                } else {
                    *(float2*)&C[(size_t)r * N + cc] = make_float2(v0, v1);
                }
            }
        }
    }
}

// ================= mma.sync tf32 flash attention (round-4 proven) =========
#define AKS 0
#define AVT (64 * 36)
#define APS (AVT + 32 * 68)
#define ATOT_FLOATS (APS + 128 * 68)
#define ATOT_BYTES (ATOT_FLOATS * 4)     // 52736

__global__ void __launch_bounds__(256) attn_mma_kernel(
    const float* __restrict__ Qg, const float* __restrict__ Kg,
    const float* __restrict__ Vg, const float* __restrict__ biasg,
    float* __restrict__ ctx)
{
    extern __shared__ float sm[];
    float* Ks = sm + AKS;
    float* Vt = sm + AVT;
    float* Ps = sm + APS;

    int tid  = threadIdx.x;
    int warp = tid >> 5, lane = tid & 31;
    int g = lane >> 2, q4 = lane & 3;
    int bh = blockIdx.y, qt = blockIdx.x;
    int b = bh >> 3, h = bh & 7;
    int rowbase = warp * 16;
    int rA = rowbase + g;
    int rB = rA + 8;

    const float* qb = Qg + ((size_t)bh * S_LEN + (size_t)qt * 128) * HDIM;
    const float* kb = Kg + (size_t)bh * S_LEN * HDIM;
    const float* vb = Vg + (size_t)bh * S_LEN * HDIM;
    const float* biasA = biasg + ((size_t)bh * S_LEN + (size_t)(qt * 128 + rA)) * S_LEN;
    const float* biasB = biasA + (size_t)8 * S_LEN;

    uint32_t qh[4][4], ql[4][4];
#pragma unroll
    for (int kt = 0; kt < 4; kt++) {
        float a0 = qb[rA * HDIM + kt * 8 + q4];
        float a1 = qb[rB * HDIM + kt * 8 + q4];
        float a2 = qb[rA * HDIM + kt * 8 + q4 + 4];
        float a3 = qb[rB * HDIM + kt * 8 + q4 + 4];
        qh[kt][0] = hibits(a0); ql[kt][0] = __float_as_uint(a0 - hival(a0));
        qh[kt][1] = hibits(a1); ql[kt][1] = __float_as_uint(a1 - hival(a1));
        qh[kt][2] = hibits(a2); ql[kt][2] = __float_as_uint(a2 - hival(a2));
        qh[kt][3] = hibits(a3); ql[kt][3] = __float_as_uint(a3 - hival(a3));
    }

    float mA = -1e30f, mB = -1e30f, lA = 0.0f, lB = 0.0f;
    float o[4][4];
#pragma unroll
    for (int nt = 0; nt < 4; nt++)
#pragma unroll
        for (int i = 0; i < 4; i++) o[nt][i] = 0.0f;

    int tld = tid >> 2;
    int dld = (tid & 3) * 8;

    for (int j = 0; j < 16; j++) {
        {
            const float* krow = kb + (size_t)(j * 64 + tld) * HDIM + dld;
            float4 k0 = *(const float4*)(krow);
            float4 k1 = *(const float4*)(krow + 4);
            *(float4*)(Ks + tld * 36 + dld)     = k0;
            *(float4*)(Ks + tld * 36 + dld + 4) = k1;
            const float* vrow = vb + (size_t)(j * 64 + tld) * HDIM + dld;
            float4 v0 = *(const float4*)(vrow);
            float4 v1 = *(const float4*)(vrow + 4);
            Vt[(dld + 0) * 68 + tld] = v0.x; Vt[(dld + 1) * 68 + tld] = v0.y;
            Vt[(dld + 2) * 68 + tld] = v0.z; Vt[(dld + 3) * 68 + tld] = v0.w;
            Vt[(dld + 4) * 68 + tld] = v1.x; Vt[(dld + 5) * 68 + tld] = v1.y;
            Vt[(dld + 6) * 68 + tld] = v1.z; Vt[(dld + 7) * 68 + tld] = v1.w;
        }
        __syncthreads();

        float c[8][4];
#pragma unroll
        for (int nt = 0; nt < 8; nt++) {
            float2 bA = *(const float2*)(biasA + j * 64 + nt * 8 + 2 * q4);
            float2 bB = *(const float2*)(biasB + j * 64 + nt * 8 + 2 * q4);
            c[nt][0] = bA.x; c[nt][1] = bA.y; c[nt][2] = bB.x; c[nt][3] = bB.y;
        }

#pragma unroll
        for (int nt = 0; nt < 8; nt++) {
#pragma unroll
            for (int kt = 0; kt < 4; kt++) {
                float b0 = Ks[(nt * 8 + g) * 36 + kt * 8 + q4];
                float b1 = Ks[(nt * 8 + g) * 36 + kt * 8 + q4 + 4];
                uint32_t bh0 = hibits(b0), bh1 = hibits(b1);
                uint32_t bl0 = __float_as_uint(b0 - hival(b0));
                uint32_t bl1 = __float_as_uint(b1 - hival(b1));
                mma1688(c[nt], qh[kt], bh0, bh1);
                mma1688(c[nt], qh[kt], bl0, bl1);
                mma1688(c[nt], ql[kt], bh0, bh1);
            }
        }

        float mxA = -1e30f, mxB = -1e30f;
#pragma unroll
        for (int nt = 0; nt < 8; nt++) {
            mxA = fmaxf(mxA, fmaxf(c[nt][0], c[nt][1]));
            mxB = fmaxf(mxB, fmaxf(c[nt][2], c[nt][3]));
        }
        mxA = fmaxf(mxA, __shfl_xor_sync(0xffffffffu, mxA, 1));
        mxA = fmaxf(mxA, __shfl_xor_sync(0xffffffffu, mxA, 2));
        mxB = fmaxf(mxB, __shfl_xor_sync(0xffffffffu, mxB, 1));
        mxB = fmaxf(mxB, __shfl_xor_sync(0xffffffffu, mxB, 2));
        float nmA = fmaxf(mA, mxA), nmB = fmaxf(mB, mxB);
        float corrA = __expf(mA - nmA), corrB = __expf(mB - nmB);
        mA = nmA; mB = nmB;
        float sA = 0.0f, sB = 0.0f;
#pragma unroll
        for (int nt = 0; nt < 8; nt++) {
            float p0 = __expf(c[nt][0] - nmA);
            float p1 = __expf(c[nt][1] - nmA);
            float p2 = __expf(c[nt][2] - nmB);
            float p3 = __expf(c[nt][3] - nmB);
            sA += p0 + p1; sB += p2 + p3;
            *(float2*)(Ps + rA * 68 + nt * 8 + 2 * q4) = make_float2(p0, p1);
            *(float2*)(Ps + rB * 68 + nt * 8 + 2 * q4) = make_float2(p2, p3);
        }
        sA += __shfl_xor_sync(0xffffffffu, sA, 1);
        sA += __shfl_xor_sync(0xffffffffu, sA, 2);
        sB += __shfl_xor_sync(0xffffffffu, sB, 1);
        sB += __shfl_xor_sync(0xffffffffu, sB, 2);
        lA = lA * corrA + sA;
        lB = lB * corrB + sB;
#pragma unroll
        for (int nt = 0; nt < 4; nt++) {
            o[nt][0] *= corrA; o[nt][1] *= corrA;
            o[nt][2] *= corrB; o[nt][3] *= corrB;
        }
        __syncwarp();

#pragma unroll
        for (int kk = 0; kk < 8; kk++) {
            float a0 = Ps[rA * 68 + kk * 8 + q4];
            float a1 = Ps[rB * 68 + kk * 8 + q4];
            float a2 = Ps[rA * 68 + kk * 8 + q4 + 4];
            float a3 = Ps[rB * 68 + kk * 8 + q4 + 4];
            uint32_t ah[4] = { hibits(a0), hibits(a1), hibits(a2), hibits(a3) };
            uint32_t al[4] = { __float_as_uint(a0 - hival(a0)), __float_as_uint(a1 - hival(a1)),
                               __float_as_uint(a2 - hival(a2)), __float_as_uint(a3 - hival(a3)) };
#pragma unroll
            for (int nt = 0; nt < 4; nt++) {
                float b0 = Vt[(nt * 8 + g) * 68 + kk * 8 + q4];
                float b1 = Vt[(nt * 8 + g) * 68 + kk * 8 + q4 + 4];
                uint32_t bh0 = hibits(b0), bh1 = hibits(b1);
                uint32_t bl0 = __float_as_uint(b0 - hival(b0));
                uint32_t bl1 = __float_as_uint(b1 - hival(b1));
                mma1688(o[nt], ah, bh0, bh1);
                mma1688(o[nt], ah, bl0, bl1);
                mma1688(o[nt], al, bh0, bh1);
            }
        }
        __syncthreads();
    }

    float invA = 1.0f / lA, invB = 1.0f / lB;
    float* cA = ctx + ((size_t)(qt * 128 + rA) * BATCH + b) * DMODEL + h * HDIM;
    float* cB = ctx + ((size_t)(qt * 128 + rB) * BATCH + b) * DMODEL + h * HDIM;
#pragma unroll
    for (int nt = 0; nt < 4; nt++) {
        *(float2*)(cA + nt * 8 + 2 * q4) = make_float2(o[nt][0] * invA, o[nt][1] * invA);
        *(float2*)(cB + nt * 8 + 2 * q4) = make_float2(o[nt][2] * invB, o[nt][3] * invB);
    }
}

// ---------------- launch ---------------------------------------------------
extern "C" void kernel_launch(void* const* d_in, const int* in_sizes, int n_in,
                              void* d_out, int out_size) {
    const float* src   = (const float*)d_in[0];
    const float* bias  = (const float*)d_in[1];
    const float* in_w  = (const float*)d_in[2];
    const float* in_b  = (const float*)d_in[3];
    const float* out_w = (const float*)d_in[4];
    const float* out_b = (const float*)d_in[5];
    const float* w1    = (const float*)d_in[6];
    const float* b1    = (const float*)d_in[7];
    const float* w2    = (const float*)d_in[8];
    const float* b2    = (const float*)d_in[9];
    const float* g1    = (const float*)d_in[10];
    const float* be1   = (const float*)d_in[11];
    const float* g2    = (const float*)d_in[12];
    const float* be2   = (const float*)d_in[13];
    float* out = (float*)d_out;

    float *px, *pq, *pk, *pv, *pctx, *px2, *py, *pff1;
    cudaGetSymbolAddress((void**)&px,   g_x);
    cudaGetSymbolAddress((void**)&pq,   g_q);
    cudaGetSymbolAddress((void**)&pk,   g_k);
    cudaGetSymbolAddress((void**)&pv,   g_v);
    cudaGetSymbolAddress((void**)&pctx, g_ctx);
    cudaGetSymbolAddress((void**)&px2,  g_x2);
    cudaGetSymbolAddress((void**)&py,   g_y);
    cudaGetSymbolAddress((void**)&pff1, g_ff1);

    cudaFuncSetAttribute(attn_mma_kernel, cudaFuncAttributeMaxDynamicSharedMemorySize, ATOT_BYTES);

    dim3 lnb(32, 8);
    // 1. x = LN1(src)
    ln_kernel<<<MROWS / 8, lnb>>>(src, g1, be1, px);
    // 2. qkv = x @ in_w^T + in_b, scattered straight into q/k/v head layout
    gemm_bf16_kernel<3><<<dim3(6, 64), 256>>>(px, in_w, in_b, nullptr, nullptr, pq, pk, pv, DMODEL, 3 * DMODEL);
    // 3. flash attention with bias -> ctx [S,B,D]
    attn_mma_kernel<<<dim3(8, 64), 256, ATOT_BYTES>>>(pq, pk, pv, bias, pctx);
    // 4. x2 = x + ctx @ out_w^T + out_b
    gemm_bf16_kernel<2><<<dim3(2, 64), 256>>>(pctx, out_w, out_b, px, px2, nullptr, nullptr, nullptr, DMODEL, DMODEL);
    // 5. y = LN2(x2)
    ln_kernel<<<MROWS / 8, lnb>>>(px2, g2, be2, py);
    // 6. ff1 = relu(y @ w1^T + b1)
    gemm_bf16_kernel<1><<<dim3(8, 64), 256>>>(py, w1, b1, nullptr, pff1, nullptr, nullptr, nullptr, DMODEL, DFF);
    // 7. out = y + ff1 @ w2^T + b2
    gemm_bf16_kernel<2><<<dim3(2, 64), 256>>>(pff1, w2, b2, py, out, nullptr, nullptr, nullptr, DFF, DMODEL);
}

// round 6
// speedup vs baseline: 3.2035x; 1.1931x over previous
#include <cuda_runtime.h>
#include <cuda_bf16.h>
#include <cstdint>
#include <math.h>

#define S_LEN  1024
#define BATCH  8
#define DMODEL 256
#define NH     8
#define HDIM   32
#define DFF    1024
#define MROWS  (S_LEN * BATCH)   // 8192
#define LN_EPS 1e-5f

// ---------------- scratch (no runtime allocation allowed) ----------------
__device__ float g_x  [MROWS * DMODEL];
__device__ float g_q  [BATCH * NH * S_LEN * HDIM];
__device__ float g_k  [BATCH * NH * S_LEN * HDIM];
__device__ float g_v  [BATCH * NH * S_LEN * HDIM];
__device__ float g_ctx[MROWS * DMODEL];
__device__ float g_x2 [MROWS * DMODEL];
__device__ float g_y  [MROWS * DMODEL];
__device__ float g_ff1[MROWS * DFF];

// ---------------- mma helpers ---------------------------------------------
__device__ __forceinline__ void mma16816(float* c, const uint32_t* a, uint32_t b0, uint32_t b1) {
    asm volatile(
        "mma.sync.aligned.m16n8k16.row.col.f32.bf16.bf16.f32 "
        "{%0,%1,%2,%3}, {%4,%5,%6,%7}, {%8,%9}, {%0,%1,%2,%3};"
        : "+f"(c[0]), "+f"(c[1]), "+f"(c[2]), "+f"(c[3])
        : "r"(a[0]), "r"(a[1]), "r"(a[2]), "r"(a[3]), "r"(b0), "r"(b1));
}
// split x,y into packed bf16x2 hi and lo (hi + lo ~= x with ~16 mantissa bits)
__device__ __forceinline__ void split_bf16x2(float x, float y, uint32_t& hi, uint32_t& lo) {
    __nv_bfloat162 h = __floats2bfloat162_rn(x, y);
    float hx = __bfloat162float(h.x), hy = __bfloat162float(h.y);
    __nv_bfloat162 l = __floats2bfloat162_rn(x - hx, y - hy);
    hi = *reinterpret_cast<uint32_t*>(&h);
    lo = *reinterpret_cast<uint32_t*>(&l);
}

// ---------------- LayerNorm: one warp per row ----------------------------
__global__ void ln_kernel(const float* __restrict__ in,
                          const float* __restrict__ gw,
                          const float* __restrict__ bw,
                          float* __restrict__ out) {
    int row  = blockIdx.x * blockDim.y + threadIdx.y;
    int lane = threadIdx.x;
    const float4* xp = (const float4*)(in + (size_t)row * DMODEL);
    float4 v0 = xp[lane];
    float4 v1 = xp[lane + 32];
    float s = v0.x + v0.y + v0.z + v0.w + v1.x + v1.y + v1.z + v1.w;
#pragma unroll
    for (int o = 16; o > 0; o >>= 1) s += __shfl_xor_sync(0xffffffffu, s, o);
    float mu = s * (1.0f / DMODEL);
    float d0x = v0.x - mu, d0y = v0.y - mu, d0z = v0.z - mu, d0w = v0.w - mu;
    float d1x = v1.x - mu, d1y = v1.y - mu, d1z = v1.z - mu, d1w = v1.w - mu;
    float q = d0x*d0x + d0y*d0y + d0z*d0z + d0w*d0w
            + d1x*d1x + d1y*d1y + d1z*d1z + d1w*d1w;
#pragma unroll
    for (int o = 16; o > 0; o >>= 1) q += __shfl_xor_sync(0xffffffffu, q, o);
    float rs = rsqrtf(q * (1.0f / DMODEL) + LN_EPS);
    const float4* gp = (const float4*)gw;
    const float4* bp = (const float4*)bw;
    float4 ga = gp[lane], gb = gp[lane + 32];
    float4 ba = bp[lane], bb = bp[lane + 32];
    float4 o0, o1;
    o0.x = d0x * rs * ga.x + ba.x;  o0.y = d0y * rs * ga.y + ba.y;
    o0.z = d0z * rs * ga.z + ba.z;  o0.w = d0w * rs * ga.w + ba.w;
    o1.x = d1x * rs * gb.x + bb.x;  o1.y = d1y * rs * gb.y + bb.y;
    o1.z = d1z * rs * gb.z + bb.z;  o1.w = d1w * rs * gb.w + bb.w;
    float4* op = (float4*)(out + (size_t)row * DMODEL);
    op[lane]      = o0;
    op[lane + 32] = o1;
}

// ================= bf16-split tensor GEMM (round-5 proven) =================
#define GP 20   // row pitch in uint32 (16 used)
template<int MODE>
__global__ void __launch_bounds__(256) gemm_bf16_kernel(
    const float* __restrict__ A, const float* __restrict__ W,
    const float* __restrict__ bias, const float* __restrict__ resid,
    float* __restrict__ C,
    float* __restrict__ qo, float* __restrict__ ko, float* __restrict__ vo,
    int K, int N)
{
    __shared__ uint32_t sAh[128 * GP], sAl[128 * GP];
    __shared__ uint32_t sWh[128 * GP], sWl[128 * GP];

    int tid = threadIdx.x;
    int warp = tid >> 5, lane = tid & 31;
    int g = lane >> 2, q4 = lane & 3;
    int wm = warp >> 1, wn = warp & 1;
    int m0 = wm * 32, n0 = wn * 64;
    int rowBase = blockIdx.y * 128;
    int colBase = blockIdx.x * 128;

    int lr = tid >> 1;
    int lc = (tid & 1) * 16;
    const float* Ap = A + (size_t)(rowBase + lr) * K + lc;
    const float* Wp = W + (size_t)(colBase + lr) * K + lc;
    uint32_t* sAhp = sAh + lr * GP + (tid & 1) * 8;
    uint32_t* sAlp = sAl + lr * GP + (tid & 1) * 8;
    uint32_t* sWhp = sWh + lr * GP + (tid & 1) * 8;
    uint32_t* sWlp = sWl + lr * GP + (tid & 1) * 8;

    float c[2][8][4];
#pragma unroll
    for (int mt = 0; mt < 2; mt++)
#pragma unroll
        for (int nt = 0; nt < 8; nt++)
#pragma unroll
            for (int i = 0; i < 4; i++) c[mt][nt][i] = 0.0f;

    for (int k0 = 0; k0 < K; k0 += 32) {
#pragma unroll
        for (int p = 0; p < 4; p++) {
            float4 av = *(const float4*)(Ap + k0 + p * 4);
            uint32_t h0, l0, h1, l1;
            split_bf16x2(av.x, av.y, h0, l0);
            split_bf16x2(av.z, av.w, h1, l1);
            sAhp[p * 2] = h0; sAhp[p * 2 + 1] = h1;
            sAlp[p * 2] = l0; sAlp[p * 2 + 1] = l1;
            float4 wv = *(const float4*)(Wp + k0 + p * 4);
            split_bf16x2(wv.x, wv.y, h0, l0);
            split_bf16x2(wv.z, wv.w, h1, l1);
            sWhp[p * 2] = h0; sWhp[p * 2 + 1] = h1;
            sWlp[p * 2] = l0; sWlp[p * 2 + 1] = l1;
        }
        __syncthreads();

#pragma unroll
        for (int ks = 0; ks < 2; ks++) {
            int kb = ks * 8;
            uint32_t ah[2][4], al[2][4];
#pragma unroll
            for (int mt = 0; mt < 2; mt++) {
                int r0 = (m0 + mt * 16 + g) * GP + kb + q4;
                int r1 = (m0 + mt * 16 + g + 8) * GP + kb + q4;
                ah[mt][0] = sAh[r0];     ah[mt][1] = sAh[r1];
                ah[mt][2] = sAh[r0 + 4]; ah[mt][3] = sAh[r1 + 4];
                al[mt][0] = sAl[r0];     al[mt][1] = sAl[r1];
                al[mt][2] = sAl[r0 + 4]; al[mt][3] = sAl[r1 + 4];
            }
#pragma unroll
            for (int nt = 0; nt < 8; nt++) {
                int rb = (n0 + nt * 8 + g) * GP + kb + q4;
                uint32_t bh0 = sWh[rb], bh1 = sWh[rb + 4];
                uint32_t bl0 = sWl[rb], bl1 = sWl[rb + 4];
#pragma unroll
                for (int mt = 0; mt < 2; mt++) {
                    mma16816(c[mt][nt], ah[mt], bh0, bh1);
                    mma16816(c[mt][nt], ah[mt], bl0, bl1);
                    mma16816(c[mt][nt], al[mt], bh0, bh1);
                }
            }
        }
        __syncthreads();
    }

#pragma unroll
    for (int mt = 0; mt < 2; mt++) {
#pragma unroll
        for (int half = 0; half < 2; half++) {
            int r = rowBase + m0 + mt * 16 + g + half * 8;
#pragma unroll
            for (int nt = 0; nt < 8; nt++) {
                int cc = colBase + n0 + nt * 8 + 2 * q4;
                float v0 = c[mt][nt][half * 2 + 0] + bias[cc];
                float v1 = c[mt][nt][half * 2 + 1] + bias[cc + 1];
                if (MODE == 1) { v0 = fmaxf(v0, 0.0f); v1 = fmaxf(v1, 0.0f); }
                if (MODE == 2) {
                    float2 rr = *(const float2*)&resid[(size_t)r * N + cc];
                    v0 += rr.x; v1 += rr.y;
                }
                if (MODE == 3) {
                    int s = r >> 3, b = r & 7;
                    int part = cc >> 8;
                    int h = (cc & 255) >> 5;
                    int hd = cc & 31;
                    size_t dst = ((((size_t)b * NH + h) * S_LEN + s) * HDIM) + hd;
                    if (part == 0) {
                        const float sc = 0.17677669529663687f;  // 1/sqrt(32)
                        *(float2*)&qo[dst] = make_float2(v0 * sc, v1 * sc);
                    } else if (part == 1) {
                        *(float2*)&ko[dst] = make_float2(v0, v1);
                    } else {
                        *(float2*)&vo[dst] = make_float2(v0, v1);
                    }
                } else {
                    *(float2*)&C[(size_t)r * N + cc] = make_float2(v0, v1);
                }
            }
        }
    }
}

// ================= bf16-split flash attention ==============================
// Block 256 = 8 warps, warp owns 16 q-rows; BM=128, chunk BN=64, HD=32.
// QK^T and PV via m16n8k16 bf16 hi/lo 3-MMA. P stays in registers: the
// QK C-fragment layout IS the PV A-fragment layout (rows g/g+8, col pairs 2q4).
#define PK 20    // sK pitch (uint32 pairs; 16 used)
#define PV2 36   // sVt pitch (uint32 pairs; 32 used)

__global__ void __launch_bounds__(256) attn_bf16_kernel(
    const float* __restrict__ Qg, const float* __restrict__ Kg,
    const float* __restrict__ Vg, const float* __restrict__ biasg,
    float* __restrict__ ctx)
{
    __shared__ uint32_t sKh[64 * PK], sKl[64 * PK];
    __shared__ uint32_t sVh[32 * PV2], sVl[32 * PV2];

    int tid  = threadIdx.x;
    int warp = tid >> 5, lane = tid & 31;
    int g = lane >> 2, q4 = lane & 3;
    int bh = blockIdx.y, qt = blockIdx.x;
    int b = bh >> 3, h = bh & 7;
    int rA = warp * 16 + g;
    int rB = rA + 8;

    const float* qb = Qg + ((size_t)bh * S_LEN + (size_t)qt * 128) * HDIM;
    const float* kb = Kg + (size_t)bh * S_LEN * HDIM;
    const float* vb = Vg + (size_t)bh * S_LEN * HDIM;
    const float* biasA = biasg + ((size_t)bh * S_LEN + (size_t)(qt * 128 + rA)) * S_LEN;
    const float* biasB = biasA + (size_t)8 * S_LEN;

    // ---- Q fragments (bf16 hi/lo pairs), held for whole kernel ----
    // kt selects k16 block; a0:(rA,2q4|+1) a1:(rB,..) a2:(rA,8+2q4|+1) a3:(rB,..)
    uint32_t qh[2][4], ql[2][4];
#pragma unroll
    for (int kt = 0; kt < 2; kt++) {
        int k0 = kt * 16 + 2 * q4;
        split_bf16x2(qb[rA * HDIM + k0],     qb[rA * HDIM + k0 + 1], qh[kt][0], ql[kt][0]);
        split_bf16x2(qb[rB * HDIM + k0],     qb[rB * HDIM + k0 + 1], qh[kt][1], ql[kt][1]);
        split_bf16x2(qb[rA * HDIM + k0 + 8], qb[rA * HDIM + k0 + 9], qh[kt][2], ql[kt][2]);
        split_bf16x2(qb[rB * HDIM + k0 + 8], qb[rB * HDIM + k0 + 9], qh[kt][3], ql[kt][3]);
    }

    float mA = -1e30f, mB = -1e30f, lA = 0.0f, lB = 0.0f;
    float o[4][4];
#pragma unroll
    for (int nt = 0; nt < 4; nt++)
#pragma unroll
        for (int i = 0; i < 4; i++) o[nt][i] = 0.0f;

    // stage mappings
    int tK = tid >> 2;              // 0..63   K row
    int dK = (tid & 3) * 8;         // 0,8,16,24 (d start, 8 floats)
    int uV = tid >> 3;              // 0..31   V t-pair index
    int dV = (tid & 7) * 4;         // 0..28   V d start (4 floats)

    for (int j = 0; j < 16; j++) {
        // ---- stage K chunk as [t][d-pairs] and V^T as [d][t-pairs] ----
        {
            const float* krow = kb + (size_t)(j * 64 + tK) * HDIM + dK;
            float4 k0 = *(const float4*)(krow);
            float4 k1 = *(const float4*)(krow + 4);
            uint32_t* kh = sKh + tK * PK + dK / 2;
            uint32_t* kl = sKl + tK * PK + dK / 2;
            uint32_t hh, ll;
            split_bf16x2(k0.x, k0.y, hh, ll); kh[0] = hh; kl[0] = ll;
            split_bf16x2(k0.z, k0.w, hh, ll); kh[1] = hh; kl[1] = ll;
            split_bf16x2(k1.x, k1.y, hh, ll); kh[2] = hh; kl[2] = ll;
            split_bf16x2(k1.z, k1.w, hh, ll); kh[3] = hh; kl[3] = ll;

            const float* vr0 = vb + (size_t)(j * 64 + 2 * uV) * HDIM + dV;
            float4 v0 = *(const float4*)(vr0);
            float4 v1 = *(const float4*)(vr0 + HDIM);
#pragma unroll
            for (int i = 0; i < 4; i++) {
                float a = (i == 0) ? v0.x : (i == 1) ? v0.y : (i == 2) ? v0.z : v0.w;
                float bb2 = (i == 0) ? v1.x : (i == 1) ? v1.y : (i == 2) ? v1.z : v1.w;
                split_bf16x2(a, bb2, hh, ll);
                sVh[(dV + i) * PV2 + uV] = hh;
                sVl[(dV + i) * PV2 + uV] = ll;
            }
        }
        __syncthreads();

        // ---- C fragments initialized with bias (read once from DRAM) ----
        float c[8][4];
#pragma unroll
        for (int nt = 0; nt < 8; nt++) {
            float2 bA = *(const float2*)(biasA + j * 64 + nt * 8 + 2 * q4);
            float2 bB = *(const float2*)(biasB + j * 64 + nt * 8 + 2 * q4);
            c[nt][0] = bA.x; c[nt][1] = bA.y; c[nt][2] = bB.x; c[nt][3] = bB.y;
        }

        // ---- QK^T: 8 n-tiles x 2 k16-steps x 3 split-MMAs ----
#pragma unroll
        for (int nt = 0; nt < 8; nt++) {
#pragma unroll
            for (int kt = 0; kt < 2; kt++) {
                int rb = (nt * 8 + g) * PK + kt * 8 + q4;
                uint32_t bh0 = sKh[rb], bh1 = sKh[rb + 4];
                uint32_t bl0 = sKl[rb], bl1 = sKl[rb + 4];
                mma16816(c[nt], qh[kt], bh0, bh1);
                mma16816(c[nt], qh[kt], bl0, bl1);
                mma16816(c[nt], ql[kt], bh0, bh1);
            }
        }

        // ---- online softmax (rows rA, rB; quad of 4 lanes) ----
        float mxA = -1e30f, mxB = -1e30f;
#pragma unroll
        for (int nt = 0; nt < 8; nt++) {
            mxA = fmaxf(mxA, fmaxf(c[nt][0], c[nt][1]));
            mxB = fmaxf(mxB, fmaxf(c[nt][2], c[nt][3]));
        }
        mxA = fmaxf(mxA, __shfl_xor_sync(0xffffffffu, mxA, 1));
        mxA = fmaxf(mxA, __shfl_xor_sync(0xffffffffu, mxA, 2));
        mxB = fmaxf(mxB, __shfl_xor_sync(0xffffffffu, mxB, 1));
        mxB = fmaxf(mxB, __shfl_xor_sync(0xffffffffu, mxB, 2));
        float nmA = fmaxf(mA, mxA), nmB = fmaxf(mB, mxB);
        float corrA = __expf(mA - nmA), corrB = __expf(mB - nmB);
        mA = nmA; mB = nmB;
        float sA = 0.0f, sB = 0.0f;
#pragma unroll
        for (int nt = 0; nt < 8; nt++) {
            c[nt][0] = __expf(c[nt][0] - nmA);
            c[nt][1] = __expf(c[nt][1] - nmA);
            c[nt][2] = __expf(c[nt][2] - nmB);
            c[nt][3] = __expf(c[nt][3] - nmB);
            sA += c[nt][0] + c[nt][1];
            sB += c[nt][2] + c[nt][3];
        }
        sA += __shfl_xor_sync(0xffffffffu, sA, 1);
        sA += __shfl_xor_sync(0xffffffffu, sA, 2);
        sB += __shfl_xor_sync(0xffffffffu, sB, 1);
        sB += __shfl_xor_sync(0xffffffffu, sB, 2);
        lA = lA * corrA + sA;
        lB = lB * corrB + sB;
#pragma unroll
        for (int nt = 0; nt < 4; nt++) {
            o[nt][0] *= corrA; o[nt][1] *= corrA;
            o[nt][2] *= corrB; o[nt][3] *= corrB;
        }

        // ---- repack P (C-frag) -> PV A-frags in registers, split hi/lo ----
        uint32_t ph[4][4], pl[4][4];
#pragma unroll
        for (int kk = 0; kk < 4; kk++) {
            split_bf16x2(c[2 * kk][0],     c[2 * kk][1],     ph[kk][0], pl[kk][0]);
            split_bf16x2(c[2 * kk][2],     c[2 * kk][3],     ph[kk][1], pl[kk][1]);
            split_bf16x2(c[2 * kk + 1][0], c[2 * kk + 1][1], ph[kk][2], pl[kk][2]);
            split_bf16x2(c[2 * kk + 1][2], c[2 * kk + 1][3], ph[kk][3], pl[kk][3]);
        }

        // ---- PV: 4 k16-steps x 4 n-tiles x 3 split-MMAs ----
#pragma unroll
        for (int kk = 0; kk < 4; kk++) {
#pragma unroll
            for (int nt = 0; nt < 4; nt++) {
                int rb = (nt * 8 + g) * PV2 + kk * 8 + q4;
                uint32_t bh0 = sVh[rb], bh1 = sVh[rb + 4];
                uint32_t bl0 = sVl[rb], bl1 = sVl[rb + 4];
                mma16816(o[nt], ph[kk], bh0, bh1);
                mma16816(o[nt], ph[kk], bl0, bl1);
                mma16816(o[nt], pl[kk], bh0, bh1);
            }
        }
        __syncthreads();
    }

    // ---- epilogue: normalize, write ctx[S,B,D] ----
    float invA = 1.0f / lA, invB = 1.0f / lB;
    float* cA = ctx + ((size_t)(qt * 128 + rA) * BATCH + b) * DMODEL + h * HDIM;
    float* cB = ctx + ((size_t)(qt * 128 + rB) * BATCH + b) * DMODEL + h * HDIM;
#pragma unroll
    for (int nt = 0; nt < 4; nt++) {
        *(float2*)(cA + nt * 8 + 2 * q4) = make_float2(o[nt][0] * invA, o[nt][1] * invA);
        *(float2*)(cB + nt * 8 + 2 * q4) = make_float2(o[nt][2] * invB, o[nt][3] * invB);
    }
}

// ---------------- launch ---------------------------------------------------
extern "C" void kernel_launch(void* const* d_in, const int* in_sizes, int n_in,
                              void* d_out, int out_size) {
    const float* src   = (const float*)d_in[0];
    const float* bias  = (const float*)d_in[1];
    const float* in_w  = (const float*)d_in[2];
    const float* in_b  = (const float*)d_in[3];
    const float* out_w = (const float*)d_in[4];
    const float* out_b = (const float*)d_in[5];
    const float* w1    = (const float*)d_in[6];
    const float* b1    = (const float*)d_in[7];
    const float* w2    = (const float*)d_in[8];
    const float* b2    = (const float*)d_in[9];
    const float* g1    = (const float*)d_in[10];
    const float* be1   = (const float*)d_in[11];
    const float* g2    = (const float*)d_in[12];
    const float* be2   = (const float*)d_in[13];
    float* out = (float*)d_out;

    float *px, *pq, *pk, *pv, *pctx, *px2, *py, *pff1;
    cudaGetSymbolAddress((void**)&px,   g_x);
    cudaGetSymbolAddress((void**)&pq,   g_q);
    cudaGetSymbolAddress((void**)&pk,   g_k);
    cudaGetSymbolAddress((void**)&pv,   g_v);
    cudaGetSymbolAddress((void**)&pctx, g_ctx);
    cudaGetSymbolAddress((void**)&px2,  g_x2);
    cudaGetSymbolAddress((void**)&py,   g_y);
    cudaGetSymbolAddress((void**)&pff1, g_ff1);

    dim3 lnb(32, 8);
    // 1. x = LN1(src)
    ln_kernel<<<MROWS / 8, lnb>>>(src, g1, be1, px);
    // 2. qkv = x @ in_w^T + in_b, scattered straight into q/k/v head layout
    gemm_bf16_kernel<3><<<dim3(6, 64), 256>>>(px, in_w, in_b, nullptr, nullptr, pq, pk, pv, DMODEL, 3 * DMODEL);
    // 3. flash attention with bias -> ctx [S,B,D]
    attn_bf16_kernel<<<dim3(8, 64), 256>>>(pq, pk, pv, bias, pctx);
    // 4. x2 = x + ctx @ out_w^T + out_b
    gemm_bf16_kernel<2><<<dim3(2, 64), 256>>>(pctx, out_w, out_b, px, px2, nullptr, nullptr, nullptr, DMODEL, DMODEL);
    // 5. y = LN2(x2)
    ln_kernel<<<MROWS / 8, lnb>>>(px2, g2, be2, py);
    // 6. ff1 = relu(y @ w1^T + b1)
    gemm_bf16_kernel<1><<<dim3(8, 64), 256>>>(py, w1, b1, nullptr, pff1, nullptr, nullptr, nullptr, DMODEL, DFF);
    // 7. out = y + ff1 @ w2^T + b2
    gemm_bf16_kernel<2><<<dim3(2, 64), 256>>>(pff1, w2, b2, py, out, nullptr, nullptr, nullptr, DFF, DMODEL);
}